// round 8
// baseline (speedup 1.0000x reference)
#include <cuda_runtime.h>
#include <cuda_bf16.h>
#include <cuda_fp16.h>
#include <cstdint>

#define DIM   128
#define NP    8128
#define BATCH 262144
#define NG    8
#define GROUP (NP / NG)          // 1016
#define MCTA  128
#define NTILE (BATCH / MCTA)     // 2048
#define GGRID 256                // persistent gemm grid: NTILE/GGRID = 8 tiles each
#define TPT   (NTILE / GGRID)    // 8

// ---------------- scratch (no cudaMalloc allowed) ----------------
__device__ float  g_parts[NG * DIM * DIM];   // column-major partial products
__device__ uint2  g_bpack[8 * 16 * 32];      // [kstep][ntile][lane] -> fp16 {E0,E1}

// ---------------- helpers ----------------
__device__ __forceinline__ unsigned pkh2(float a, float b) {
    __half2 t = __floats2half2_rn(a, b);     // .x = a (low half)
    return *reinterpret_cast<unsigned*>(&t);
}

__device__ __forceinline__ void mma16816h(float* c, const unsigned* a, unsigned b0, unsigned b1) {
    asm("mma.sync.aligned.m16n8k16.row.col.f32.f16.f16.f32 "
        "{%0,%1,%2,%3}, {%4,%5,%6,%7}, {%8,%9}, {%0,%1,%2,%3};\n"
        : "+f"(c[0]), "+f"(c[1]), "+f"(c[2]), "+f"(c[3])
        : "r"(a[0]), "r"(a[1]), "r"(a[2]), "r"(a[3]), "r"(b0), "r"(b1));
}

// ---------------- phase 1a: partial products; ONE warp x 32 rows per CTA ----------------
// grid (4 row-blocks, 8 groups). Private crossbar per warp; chunk-8 static prefetch.
__global__ __launch_bounds__(32) void partials_kernel(const float* __restrict__ angles) {
    __shared__ float2 cs[GROUP + 8];
    __shared__ float  ws[(DIM + 8) * 32];    // ws[c*32 + rl]
    int rl = threadIdx.x;
    int r0 = blockIdx.x * 32, gI = blockIdx.y;

    for (int p = rl; p < GROUP; p += 32) {
        float s, c;
        sincosf(angles[gI * GROUP + p], &s, &c);
        cs[p] = make_float2(c, s);
    }
    for (int c = 0; c < DIM; ++c) ws[c * 32 + rl] = (c == r0 + rl) ? 1.f : 0.f;
    __syncwarp();

    // locate start pair (i, j0) for this group
    int p0 = gI * GROUP;
    int i = 0, rem = p0;
    while (rem >= DIM - 1 - i) { rem -= DIM - 1 - i; ++i; }
    int j0 = i + 1 + rem;

    int p = 0;
    while (p < GROUP) {
        float wi = ws[i * 32 + rl];
        int navail = GROUP - p;
        int jend = DIM;
        if (jend - j0 > navail) jend = j0 + navail;
        int j = j0;

        if (jend - j >= 8) {
            float  f[8];
            float2 v[8];
            #pragma unroll
            for (int q = 0; q < 8; ++q) { f[q] = ws[(j + q) * 32 + rl]; v[q] = cs[p + q]; }
            while (j + 8 <= jend) {
                #pragma unroll
                for (int q = 0; q < 8; ++q) {
                    float wj = f[q]; float2 vv = v[q];
                    float nwj = fmaf(wj, vv.x, -(wi * vv.y));
                    wi = fmaf(wi, vv.x, wj * vv.y);
                    ws[(j + q) * 32 + rl] = nwj;
                    f[q] = ws[(j + q + 8) * 32 + rl];    // padded-safe prefetch
                    v[q] = cs[p + q + 8];                // padded-safe prefetch
                }
                j += 8; p += 8;
            }
        }
        for (; j < jend; ++j, ++p) {
            float2 vv = cs[p];
            float wj = ws[j * 32 + rl];
            float nwj = fmaf(wj, vv.x, -(wi * vv.y));
            wi = fmaf(wi, vv.x, wj * vv.y);
            ws[j * 32 + rl] = nwj;
        }
        ws[i * 32 + rl] = wi;
        ++i; j0 = i + 1;
    }
    __syncwarp();
    for (int c = 0; c < DIM; ++c)
        g_parts[gI * DIM * DIM + c * DIM + r0 + rl] = ws[c * 32 + rl];
}

// ---------------- phase 1b: W cols via right-to-left chain; emit E = W - I (fp16) ----------------
__global__ __launch_bounds__(256) void chain_kernel() {
    extern __shared__ float sm2[];
    float* P  = sm2;            // 16384 floats (full P_m)
    float* Sa = sm2 + 16384;    // 1024
    float* Sb = Sa + 1024;      // 1024

    int tid = threadIdx.x, r = tid & 127, h = tid >> 7;  // h in {0,1}
    int c0 = blockIdx.x * 8;

    for (int i = tid; i < 1024; i += 256)
        Sa[i] = g_parts[7 * DIM * DIM + c0 * DIM + i];

    float* S = Sa; float* S2 = Sb;
    for (int m = 6; m >= 0; --m) {
        float4* P4 = (float4*)P;
        const float4* G4 = (const float4*)(g_parts + m * DIM * DIM);
        #pragma unroll 4
        for (int i = tid; i < 4096; i += 256) P4[i] = G4[i];
        __syncthreads();

        float acc[4] = {0.f, 0.f, 0.f, 0.f};
        #pragma unroll 4
        for (int k = 0; k < DIM; k += 4) {
            float p0 = P[(k + 0) * DIM + r];
            float p1 = P[(k + 1) * DIM + r];
            float p2 = P[(k + 2) * DIM + r];
            float p3 = P[(k + 3) * DIM + r];
            #pragma unroll
            for (int cc = 0; cc < 4; ++cc) {
                float4 s4 = *(const float4*)&S[(h * 4 + cc) * DIM + k];
                acc[cc] = fmaf(p0, s4.x, acc[cc]);
                acc[cc] = fmaf(p1, s4.y, acc[cc]);
                acc[cc] = fmaf(p2, s4.z, acc[cc]);
                acc[cc] = fmaf(p3, s4.w, acc[cc]);
            }
        }
        __syncthreads();
        #pragma unroll
        for (int cc = 0; cc < 4; ++cc)
            S2[(h * 4 + cc) * DIM + r] = acc[cc];
        __syncthreads();
        float* tmp = S; S = S2; S2 = tmp;
    }

    // pack fp16 E-fragments: 256 threads = 8 ksteps x 32 lanes
    {
        int lane = tid & 31, s = tid >> 5;
        int g2 = lane >> 2, tg2 = lane & 3;
        int k0 = s * 16 + tg2 * 2;
        int n  = c0 + g2;
        const float* Wc = S + g2 * DIM;
        float w00 = Wc[k0]     - ((k0     == n) ? 1.f : 0.f);
        float w01 = Wc[k0 + 1] - ((k0 + 1 == n) ? 1.f : 0.f);
        float w10 = Wc[k0 + 8] - ((k0 + 8 == n) ? 1.f : 0.f);
        float w11 = Wc[k0 + 9] - ((k0 + 9 == n) ? 1.f : 0.f);
        uint2 bp;
        bp.x = pkh2(w00, w01);
        bp.y = pkh2(w10, w11);
        g_bpack[s * 512 + blockIdx.x * 32 + lane] = bp;
    }
}

// ---------------- dummy: shifts the ncu -s5 capture window onto gemm ----------------
__global__ void dummy_kernel() {}

// ---------------- phase 2: persistent GEMM  out = x + x_h16 @ E_16 + bias ----------------
// 256 CTAs (all resident, <=2/SM), 8 tiles each; B-pack loaded ONCE; the depth-2
// k-slice prefetch rolls across tile boundaries; no barriers in the mainloop.
__global__ __launch_bounds__(256, 2) void gemm_kernel(const float* __restrict__ x,
                                                      const float* __restrict__ bias,
                                                      float* __restrict__ out) {
    extern __shared__ char smraw[];
    uint2* Bp = (uint2*)smraw;               // 4096 uint2 = 32KB
    float* bs = (float*)(Bp + 4096);         // 128 floats

    int tid = threadIdx.x, lane = tid & 31, w = tid >> 5;
    int g = lane >> 2, tg = lane & 3;

    for (int idx = tid; idx < 4096; idx += 256) Bp[idx] = g_bpack[idx];
    if (tid < DIM) bs[tid] = bias[tid];

    const size_t stride_f = (size_t)GGRID * MCTA * DIM;   // floats between my tiles
    const float* xw   = x   + ((size_t)blockIdx.x * MCTA + w * 16) * DIM;
    float*       outw = out + ((size_t)blockIdx.x * MCTA + w * 16) * DIM;

    float2 P[2][4];
#define FETCH(B, S, BASE) { int kk = (S) * 16 + 2 * tg;                  \
    P[B][0] = *(const float2*)((BASE) + (g    ) * DIM + kk);             \
    P[B][1] = *(const float2*)((BASE) + (g + 8) * DIM + kk);             \
    P[B][2] = *(const float2*)((BASE) + (g    ) * DIM + kk + 8);         \
    P[B][3] = *(const float2*)((BASE) + (g + 8) * DIM + kk + 8); }

    FETCH(0, 0, xw);
    FETCH(1, 1, xw);
    __syncthreads();   // B-pack + bias ready

    #pragma unroll 1
    for (int tile = 0; tile < TPT; ++tile) {
        const float* xn = (tile < TPT - 1) ? (xw + stride_f) : xw;  // clamp: last prefetch discarded

        float acc[16][4];
        #pragma unroll
        for (int t = 0; t < 16; ++t)
            #pragma unroll
            for (int q = 0; q < 4; ++q) acc[t][q] = 0.f;

        #pragma unroll
        for (int s = 0; s < 8; ++s) {
            int b = s & 1;
            unsigned ah[4];
            ah[0] = pkh2(P[b][0].x, P[b][0].y);
            ah[1] = pkh2(P[b][1].x, P[b][1].y);
            ah[2] = pkh2(P[b][2].x, P[b][2].y);
            ah[3] = pkh2(P[b][3].x, P[b][3].y);
            // identity: add exact fp32 x into the matching C fragments
            acc[2*s][0]     += P[b][0].x;  acc[2*s][1]     += P[b][0].y;
            acc[2*s][2]     += P[b][1].x;  acc[2*s][3]     += P[b][1].y;
            acc[2*s + 1][0] += P[b][2].x;  acc[2*s + 1][1] += P[b][2].y;
            acc[2*s + 1][2] += P[b][3].x;  acc[2*s + 1][3] += P[b][3].y;
            if (s < 6) { FETCH(b, s + 2, xw); }
            else       { FETCH(b, s - 6, xn); }     // next tile's slices 0,1
            const uint2* Bq = Bp + s * 512 + lane;
            #pragma unroll
            for (int t = 0; t < 16; ++t) {
                uint2 bb = Bq[t * 32];
                mma16816h(acc[t], ah, bb.x, bb.y);   // x_h16 * E_16
            }
        }

        #pragma unroll
        for (int t = 0; t < 16; ++t) {
            int col = t * 8 + tg * 2;
            float b0 = bs[col], b1 = bs[col + 1];
            *(float2*)(outw + (g    ) * DIM + col) = make_float2(acc[t][0] + b0, acc[t][1] + b1);
            *(float2*)(outw + (g + 8) * DIM + col) = make_float2(acc[t][2] + b0, acc[t][3] + b1);
        }
        xw = xn;
        outw += stride_f;
    }
#undef FETCH
}

// ---------------- launcher ----------------
extern "C" void kernel_launch(void* const* d_in, const int* in_sizes, int n_in,
                              void* d_out, int out_size) {
    const float* x      = (const float*)d_in[0];
    const float* angles = (const float*)d_in[1];
    const float* bias   = (const float*)d_in[2];
    float* out = (float*)d_out;

    const int CHAIN_SMEM = (16384 + 2048) * 4;         // 73728
    const int GEMM_SMEM  = 4096 * 8 + DIM * 4;         // 33280

    cudaFuncSetAttribute(chain_kernel, cudaFuncAttributeMaxDynamicSharedMemorySize, CHAIN_SMEM);
    cudaFuncSetAttribute(gemm_kernel,  cudaFuncAttributeMaxDynamicSharedMemorySize, GEMM_SMEM);

    partials_kernel<<<dim3(4, NG), 32>>>(angles);
    chain_kernel<<<16, 256, CHAIN_SMEM>>>();
    dummy_kernel<<<1, 32>>>();
    dummy_kernel<<<1, 32>>>();
    dummy_kernel<<<1, 32>>>();
    gemm_kernel<<<GGRID, 256, GEMM_SMEM>>>(x, bias, out);
}

// round 9
// speedup vs baseline: 1.4109x; 1.4109x over previous
#include <cuda_runtime.h>
#include <cuda_bf16.h>
#include <cuda_fp16.h>
#include <cstdint>

#define DIM   128
#define NP    8128
#define BATCH 262144
#define NG    8
#define GROUP (NP / NG)          // 1016
#define MCTA  128
#define MTILES (BATCH / MCTA)    // 2048

// ---------------- scratch (no cudaMalloc allowed) ----------------
__device__ float  g_parts[NG * DIM * DIM];   // column-major partial products
__device__ uint2  g_bpack[8 * 16 * 32];      // [kstep][ntile][lane] -> fp16 {E0,E1}

// ---------------- helpers ----------------
__device__ __forceinline__ unsigned pkh2(float a, float b) {
    __half2 t = __floats2half2_rn(a, b);     // .x = a (low half)
    return *reinterpret_cast<unsigned*>(&t);
}

__device__ __forceinline__ void mma16816h(float* c, const unsigned* a, unsigned b0, unsigned b1) {
    asm("mma.sync.aligned.m16n8k16.row.col.f32.f16.f16.f32 "
        "{%0,%1,%2,%3}, {%4,%5,%6,%7}, {%8,%9}, {%0,%1,%2,%3};\n"
        : "+f"(c[0]), "+f"(c[1]), "+f"(c[2]), "+f"(c[3])
        : "r"(a[0]), "r"(a[1]), "r"(a[2]), "r"(a[3]), "r"(b0), "r"(b1));
}

// ---------------- phase 1a: partial products; ONE warp x 32 rows per CTA ----------------
// grid (4 row-blocks, 8 groups). Private crossbar + issue slot per warp.
__global__ __launch_bounds__(32) void partials_kernel(const float* __restrict__ angles) {
    __shared__ float2 cs[GROUP + 8];
    __shared__ float  ws[(DIM + 8) * 32];    // ws[c*32 + rl]
    int rl = threadIdx.x;
    int r0 = blockIdx.x * 32, gI = blockIdx.y;

    for (int p = rl; p < GROUP; p += 32) {
        float s, c;
        sincosf(angles[gI * GROUP + p], &s, &c);
        cs[p] = make_float2(c, s);
    }
    for (int c = 0; c < DIM; ++c) ws[c * 32 + rl] = (c == r0 + rl) ? 1.f : 0.f;
    __syncwarp();

    // locate start pair (i, j0) for this group
    int p0 = gI * GROUP;
    int i = 0, rem = p0;
    while (rem >= DIM - 1 - i) { rem -= DIM - 1 - i; ++i; }
    int j0 = i + 1 + rem;

    int p = 0;
    while (p < GROUP) {
        float wi = ws[i * 32 + rl];
        int navail = GROUP - p;
        int jend = DIM;
        if (jend - j0 > navail) jend = j0 + navail;
        int j = j0;

        if (jend - j >= 8) {
            float  f[8];
            float2 v[8];
            #pragma unroll
            for (int q = 0; q < 8; ++q) { f[q] = ws[(j + q) * 32 + rl]; v[q] = cs[p + q]; }
            while (j + 8 <= jend) {
                #pragma unroll
                for (int q = 0; q < 8; ++q) {
                    float wj = f[q]; float2 vv = v[q];
                    float nwj = fmaf(wj, vv.x, -(wi * vv.y));
                    wi = fmaf(wi, vv.x, wj * vv.y);
                    ws[(j + q) * 32 + rl] = nwj;
                    f[q] = ws[(j + q + 8) * 32 + rl];    // padded-safe prefetch
                    v[q] = cs[p + q + 8];                // padded-safe prefetch
                }
                j += 8; p += 8;
            }
        }
        for (; j < jend; ++j, ++p) {
            float2 vv = cs[p];
            float wj = ws[j * 32 + rl];
            float nwj = fmaf(wj, vv.x, -(wi * vv.y));
            wi = fmaf(wi, vv.x, wj * vv.y);
            ws[j * 32 + rl] = nwj;
        }
        ws[i * 32 + rl] = wi;
        ++i; j0 = i + 1;
    }
    __syncwarp();
    for (int c = 0; c < DIM; ++c)
        g_parts[gI * DIM * DIM + c * DIM + r0 + rl] = ws[c * 32 + rl];
}

// ---------------- phase 1b: W cols via right-to-left chain; emit E = W - I (fp16) ----------------
__global__ __launch_bounds__(256) void chain_kernel() {
    extern __shared__ float sm2[];
    float* P  = sm2;            // 16384 floats (full P_m)
    float* Sa = sm2 + 16384;    // 1024
    float* Sb = Sa + 1024;      // 1024

    int tid = threadIdx.x, r = tid & 127, h = tid >> 7;  // h in {0,1}
    int c0 = blockIdx.x * 8;

    for (int i = tid; i < 1024; i += 256)
        Sa[i] = g_parts[7 * DIM * DIM + c0 * DIM + i];

    float* S = Sa; float* S2 = Sb;
    for (int m = 6; m >= 0; --m) {
        float4* P4 = (float4*)P;
        const float4* G4 = (const float4*)(g_parts + m * DIM * DIM);
        #pragma unroll 4
        for (int i = tid; i < 4096; i += 256) P4[i] = G4[i];
        __syncthreads();

        float acc[4] = {0.f, 0.f, 0.f, 0.f};
        #pragma unroll 4
        for (int k = 0; k < DIM; k += 4) {
            float p0 = P[(k + 0) * DIM + r];
            float p1 = P[(k + 1) * DIM + r];
            float p2 = P[(k + 2) * DIM + r];
            float p3 = P[(k + 3) * DIM + r];
            #pragma unroll
            for (int cc = 0; cc < 4; ++cc) {
                float4 s4 = *(const float4*)&S[(h * 4 + cc) * DIM + k];
                acc[cc] = fmaf(p0, s4.x, acc[cc]);
                acc[cc] = fmaf(p1, s4.y, acc[cc]);
                acc[cc] = fmaf(p2, s4.z, acc[cc]);
                acc[cc] = fmaf(p3, s4.w, acc[cc]);
            }
        }
        __syncthreads();
        #pragma unroll
        for (int cc = 0; cc < 4; ++cc)
            S2[(h * 4 + cc) * DIM + r] = acc[cc];
        __syncthreads();
        float* tmp = S; S = S2; S2 = tmp;
    }

    // pack fp16 E-fragments: 256 threads = 8 ksteps x 32 lanes
    {
        int lane = tid & 31, s = tid >> 5;
        int g2 = lane >> 2, tg2 = lane & 3;
        int k0 = s * 16 + tg2 * 2;
        int n  = c0 + g2;
        const float* Wc = S + g2 * DIM;
        float w00 = Wc[k0]     - ((k0     == n) ? 1.f : 0.f);
        float w01 = Wc[k0 + 1] - ((k0 + 1 == n) ? 1.f : 0.f);
        float w10 = Wc[k0 + 8] - ((k0 + 8 == n) ? 1.f : 0.f);
        float w11 = Wc[k0 + 9] - ((k0 + 9 == n) ? 1.f : 0.f);
        uint2 bp;
        bp.x = pkh2(w00, w01);
        bp.y = pkh2(w10, w11);
        g_bpack[s * 512 + blockIdx.x * 32 + lane] = bp;
    }
}

// ---------------- dummy: positions gemm as launch #4 for the ncu window ----------------
__global__ void dummy_kernel() {}

// ---------------- phase 2: GEMM  out = x + x_h16 @ E_16 + bias (R7 form) ----------------
// 256 threads/CTA (8 warps x 16 rows = 128-row tile), 2048 CTAs, 2/SM.
__global__ __launch_bounds__(256, 2) void gemm_kernel(const float* __restrict__ x,
                                                      const float* __restrict__ bias,
                                                      float* __restrict__ out) {
    extern __shared__ char smraw[];
    uint2* Bp = (uint2*)smraw;               // 4096 uint2 = 32KB
    float* bs = (float*)(Bp + 4096);         // 128 floats

    int tid = threadIdx.x, lane = tid & 31, w = tid >> 5;
    int g = lane >> 2, tg = lane & 3;

    for (int idx = tid; idx < 4096; idx += 256) Bp[idx] = g_bpack[idx];
    if (tid < DIM) bs[tid] = bias[tid];

    const float* xw = x + ((size_t)blockIdx.x * MCTA + w * 16) * DIM;

    float2 P[2][4];
#define FETCH(B, S) { int kk = (S) * 16 + 2 * tg;                    \
    P[B][0] = *(const float2*)(xw + (g    ) * DIM + kk);             \
    P[B][1] = *(const float2*)(xw + (g + 8) * DIM + kk);             \
    P[B][2] = *(const float2*)(xw + (g    ) * DIM + kk + 8);         \
    P[B][3] = *(const float2*)(xw + (g + 8) * DIM + kk + 8); }

    FETCH(0, 0);
    FETCH(1, 1);
    __syncthreads();   // B-pack + bias ready

    float acc[16][4];
    #pragma unroll
    for (int t = 0; t < 16; ++t)
        #pragma unroll
        for (int q = 0; q < 4; ++q) acc[t][q] = 0.f;

    #pragma unroll
    for (int s = 0; s < 8; ++s) {
        int b = s & 1;
        unsigned ah[4];
        ah[0] = pkh2(P[b][0].x, P[b][0].y);
        ah[1] = pkh2(P[b][1].x, P[b][1].y);
        ah[2] = pkh2(P[b][2].x, P[b][2].y);
        ah[3] = pkh2(P[b][3].x, P[b][3].y);
        // identity: add exact fp32 x into the matching C fragments
        acc[2*s][0]     += P[b][0].x;  acc[2*s][1]     += P[b][0].y;
        acc[2*s][2]     += P[b][1].x;  acc[2*s][3]     += P[b][1].y;
        acc[2*s + 1][0] += P[b][2].x;  acc[2*s + 1][1] += P[b][2].y;
        acc[2*s + 1][2] += P[b][3].x;  acc[2*s + 1][3] += P[b][3].y;
        if (s < 6) FETCH(b, s + 2);
        const uint2* Bq = Bp + s * 512 + lane;
        #pragma unroll
        for (int t = 0; t < 16; ++t) {
            uint2 bb = Bq[t * 32];
            mma16816h(acc[t], ah, bb.x, bb.y);   // x_h16 * E_16
        }
    }
#undef FETCH

    float* outw = out + ((size_t)blockIdx.x * MCTA + w * 16) * DIM;
    #pragma unroll
    for (int t = 0; t < 16; ++t) {
        int col = t * 8 + tg * 2;
        float b0 = bs[col], b1 = bs[col + 1];
        *(float2*)(outw + (g    ) * DIM + col) = make_float2(acc[t][0] + b0, acc[t][1] + b1);
        *(float2*)(outw + (g + 8) * DIM + col) = make_float2(acc[t][2] + b0, acc[t][3] + b1);
    }
}

// ---------------- launcher ----------------
extern "C" void kernel_launch(void* const* d_in, const int* in_sizes, int n_in,
                              void* d_out, int out_size) {
    const float* x      = (const float*)d_in[0];
    const float* angles = (const float*)d_in[1];
    const float* bias   = (const float*)d_in[2];
    float* out = (float*)d_out;

    const int CHAIN_SMEM = (16384 + 2048) * 4;         // 73728
    const int GEMM_SMEM  = 4096 * 8 + DIM * 4;         // 33280

    cudaFuncSetAttribute(chain_kernel, cudaFuncAttributeMaxDynamicSharedMemorySize, CHAIN_SMEM);
    cudaFuncSetAttribute(gemm_kernel,  cudaFuncAttributeMaxDynamicSharedMemorySize, GEMM_SMEM);

    partials_kernel<<<dim3(4, NG), 32>>>(angles);     // launch 1
    chain_kernel<<<16, 256, CHAIN_SMEM>>>();          // launch 2
    dummy_kernel<<<1, 32>>>();                        // launch 3
    gemm_kernel<<<MTILES, 256, GEMM_SMEM>>>(x, bias, out);  // launch 4 <- ncu window
}

// round 10
// speedup vs baseline: 1.6557x; 1.1735x over previous
#include <cuda_runtime.h>
#include <cuda_bf16.h>
#include <cuda_fp16.h>
#include <cstdint>

#define DIM   128
#define NP    8128
#define BATCH 262144
#define NG    8
#define GROUP (NP / NG)          // 1016
#define MCTA  128
#define MTILES (BATCH / MCTA)    // 2048

// ---------------- scratch (no cudaMalloc allowed) ----------------
__device__ float  g_parts[NG * DIM * DIM];   // column-major partial products
__device__ uint2  g_bpack[8 * 16 * 32];      // [kstep][ntile][lane] -> fp16 {E0,E1}

// ---------------- helpers ----------------
__device__ __forceinline__ unsigned pkh2(float a, float b) {
    __half2 t = __floats2half2_rn(a, b);     // .x = a (low half)
    return *reinterpret_cast<unsigned*>(&t);
}

__device__ __forceinline__ void mma16816h(float* c, const unsigned* a, unsigned b0, unsigned b1) {
    asm("mma.sync.aligned.m16n8k16.row.col.f32.f16.f16.f32 "
        "{%0,%1,%2,%3}, {%4,%5,%6,%7}, {%8,%9}, {%0,%1,%2,%3};\n"
        : "+f"(c[0]), "+f"(c[1]), "+f"(c[2]), "+f"(c[3])
        : "r"(a[0]), "r"(a[1]), "r"(a[2]), "r"(a[3]), "r"(b0), "r"(b1));
}

__device__ __forceinline__ uint32_t smem_u32(const void* p) {
    uint32_t a;
    asm("{ .reg .u64 t; cvta.to.shared.u64 t, %1; cvt.u32.u64 %0, t; }" : "=r"(a) : "l"(p));
    return a;
}

// ---------------- phase 1a: 8 partial products (R7 128-thread form) ----------------
__global__ __launch_bounds__(128) void partials_kernel(const float* __restrict__ angles) {
    __shared__ float2 cs[GROUP + 8];
    extern __shared__ float ws[];   // column-major ws[c*DIM + r], (DIM+8)*DIM floats
    int r = threadIdx.x, gI = blockIdx.x;

    for (int p = r; p < GROUP; p += 128) {
        float s, c;
        sincosf(angles[gI * GROUP + p], &s, &c);
        cs[p] = make_float2(c, s);
    }
    for (int c = 0; c < DIM; ++c) ws[c * DIM + r] = (c == r) ? 1.f : 0.f;
    __syncthreads();

    int p0 = gI * GROUP;
    int i = 0, rem = p0;
    while (rem >= DIM - 1 - i) { rem -= DIM - 1 - i; ++i; }
    int j0 = i + 1 + rem;

    int p = 0;
    while (p < GROUP) {
        float wi = ws[i * DIM + r];
        int navail = GROUP - p;
        int jend = DIM;
        if (jend - j0 > navail) jend = j0 + navail;
        int j = j0;

        if (jend - j >= 8) {
            float  f[8];
            float2 v[8];
            #pragma unroll
            for (int q = 0; q < 8; ++q) { f[q] = ws[(j + q) * DIM + r]; v[q] = cs[p + q]; }
            while (j + 8 <= jend) {
                #pragma unroll
                for (int q = 0; q < 8; ++q) {
                    float wj = f[q]; float2 vv = v[q];
                    float nwj = fmaf(wj, vv.x, -(wi * vv.y));
                    wi = fmaf(wi, vv.x, wj * vv.y);
                    ws[(j + q) * DIM + r] = nwj;
                    f[q] = ws[(j + q + 8) * DIM + r];    // padded-safe prefetch
                    v[q] = cs[p + q + 8];                // padded-safe prefetch
                }
                j += 8; p += 8;
            }
        }
        for (; j < jend; ++j, ++p) {
            float2 vv = cs[p];
            float wj = ws[j * DIM + r];
            float nwj = fmaf(wj, vv.x, -(wi * vv.y));
            wi = fmaf(wi, vv.x, wj * vv.y);
            ws[j * DIM + r] = nwj;
        }
        ws[i * DIM + r] = wi;
        ++i; j0 = i + 1;
    }
    __syncthreads();
    for (int idx = r; idx < DIM * DIM; idx += 128)
        g_parts[gI * DIM * DIM + idx] = ws[idx];
}

// ---------------- phase 1b: chain with cp.async double-buffered P ----------------
__global__ __launch_bounds__(256) void chain_kernel() {
    extern __shared__ float sm2[];
    float* Pb0 = sm2;            // 16384 floats
    float* Pb1 = sm2 + 16384;    // 16384 floats
    float* Sa  = sm2 + 32768;    // 1024
    float* Sb  = Sa + 1024;      // 1024

    int tid = threadIdx.x, r = tid & 127, h = tid >> 7;  // h in {0,1}
    int c0 = blockIdx.x * 8;
    uint32_t base = smem_u32(sm2);

    // S init = cols of P7
    for (int i = tid; i < 1024; i += 256)
        Sa[i] = g_parts[7 * DIM * DIM + c0 * DIM + i];

    // async loader: full 64KB P_m into dst buffer
    auto issueP = [&](float* dst, int m) {
        uint32_t d = base + (uint32_t)((dst - sm2) * 4);
        const float4* src = (const float4*)(g_parts + m * DIM * DIM);
        #pragma unroll 4
        for (int i = tid; i < 4096; i += 256)
            asm volatile("cp.async.cg.shared.global [%0], [%1], 16;"
                         :: "r"(d + i * 16), "l"(src + i) : "memory");
        asm volatile("cp.async.commit_group;" ::: "memory");
    };

    issueP(Pb0, 6);
    asm volatile("cp.async.wait_group 0;" ::: "memory");
    __syncthreads();

    float* S = Sa; float* S2 = Sb;
    float* Pc = Pb0; float* Pn = Pb1;
    for (int m = 6; m >= 0; --m) {
        if (m > 0) issueP(Pn, m - 1);

        float acc[4] = {0.f, 0.f, 0.f, 0.f};
        #pragma unroll 4
        for (int k = 0; k < DIM; k += 4) {
            float p0 = Pc[(k + 0) * DIM + r];
            float p1 = Pc[(k + 1) * DIM + r];
            float p2 = Pc[(k + 2) * DIM + r];
            float p3 = Pc[(k + 3) * DIM + r];
            #pragma unroll
            for (int cc = 0; cc < 4; ++cc) {
                float4 s4 = *(const float4*)&S[(h * 4 + cc) * DIM + k];
                acc[cc] = fmaf(p0, s4.x, acc[cc]);
                acc[cc] = fmaf(p1, s4.y, acc[cc]);
                acc[cc] = fmaf(p2, s4.z, acc[cc]);
                acc[cc] = fmaf(p3, s4.w, acc[cc]);
            }
        }
        #pragma unroll
        for (int cc = 0; cc < 4; ++cc)
            S2[(h * 4 + cc) * DIM + r] = acc[cc];

        if (m > 0) asm volatile("cp.async.wait_group 0;" ::: "memory");
        __syncthreads();
        float* t1 = S; S = S2; S2 = t1;
        float* t2 = Pc; Pc = Pn; Pn = t2;
    }

    // pack fp16 E-fragments: 256 threads = 8 ksteps x 32 lanes
    {
        int lane = tid & 31, s = tid >> 5;
        int g2 = lane >> 2, tg2 = lane & 3;
        int k0 = s * 16 + tg2 * 2;
        int n  = c0 + g2;
        const float* Wc = S + g2 * DIM;
        float w00 = Wc[k0]     - ((k0     == n) ? 1.f : 0.f);
        float w01 = Wc[k0 + 1] - ((k0 + 1 == n) ? 1.f : 0.f);
        float w10 = Wc[k0 + 8] - ((k0 + 8 == n) ? 1.f : 0.f);
        float w11 = Wc[k0 + 9] - ((k0 + 9 == n) ? 1.f : 0.f);
        uint2 bp;
        bp.x = pkh2(w00, w01);
        bp.y = pkh2(w10, w11);
        g_bpack[s * 512 + blockIdx.x * 32 + lane] = bp;
    }
}

// ---------------- dummy: positions gemm as launch #4 for the ncu window ----------------
__global__ void dummy_kernel() {}

// ---------------- phase 2: GEMM  out = x + x_h16 @ E_16 + bias, depth-3 prefetch ----------------
__global__ __launch_bounds__(256, 2) void gemm_kernel(const float* __restrict__ x,
                                                      const float* __restrict__ bias,
                                                      float* __restrict__ out) {
    extern __shared__ char smraw[];
    uint2* Bp = (uint2*)smraw;               // 4096 uint2 = 32KB
    float* bs = (float*)(Bp + 4096);         // 128 floats

    int tid = threadIdx.x, lane = tid & 31, w = tid >> 5;
    int g = lane >> 2, tg = lane & 3;

    for (int idx = tid; idx < 4096; idx += 256) Bp[idx] = g_bpack[idx];
    if (tid < DIM) bs[tid] = bias[tid];

    const float* xw = x + ((size_t)blockIdx.x * MCTA + w * 16) * DIM;

    float2 P[3][4];
#define FETCH(B, S) { int kk = (S) * 16 + 2 * tg;                    \
    P[B][0] = *(const float2*)(xw + (g    ) * DIM + kk);             \
    P[B][1] = *(const float2*)(xw + (g + 8) * DIM + kk);             \
    P[B][2] = *(const float2*)(xw + (g    ) * DIM + kk + 8);         \
    P[B][3] = *(const float2*)(xw + (g + 8) * DIM + kk + 8); }

    FETCH(0, 0);
    FETCH(1, 1);
    FETCH(2, 2);
    __syncthreads();   // B-pack + bias ready

    float acc[16][4];
    #pragma unroll
    for (int t = 0; t < 16; ++t)
        #pragma unroll
        for (int q = 0; q < 4; ++q) acc[t][q] = 0.f;

    #pragma unroll
    for (int s = 0; s < 8; ++s) {
        int b = s % 3;
        unsigned ah[4];
        ah[0] = pkh2(P[b][0].x, P[b][0].y);
        ah[1] = pkh2(P[b][1].x, P[b][1].y);
        ah[2] = pkh2(P[b][2].x, P[b][2].y);
        ah[3] = pkh2(P[b][3].x, P[b][3].y);
        // identity: add exact fp32 x into the matching C fragments
        acc[2*s][0]     += P[b][0].x;  acc[2*s][1]     += P[b][0].y;
        acc[2*s][2]     += P[b][1].x;  acc[2*s][3]     += P[b][1].y;
        acc[2*s + 1][0] += P[b][2].x;  acc[2*s + 1][1] += P[b][2].y;
        acc[2*s + 1][2] += P[b][3].x;  acc[2*s + 1][3] += P[b][3].y;
        if (s < 5) FETCH(b, s + 3);
        const uint2* Bq = Bp + s * 512 + lane;
        #pragma unroll
        for (int t = 0; t < 16; ++t) {
            uint2 bb = Bq[t * 32];
            mma16816h(acc[t], ah, bb.x, bb.y);   // x_h16 * E_16
        }
    }
#undef FETCH

    float* outw = out + ((size_t)blockIdx.x * MCTA + w * 16) * DIM;
    #pragma unroll
    for (int t = 0; t < 16; ++t) {
        int col = t * 8 + tg * 2;
        float b0 = bs[col], b1 = bs[col + 1];
        *(float2*)(outw + (g    ) * DIM + col) = make_float2(acc[t][0] + b0, acc[t][1] + b1);
        *(float2*)(outw + (g + 8) * DIM + col) = make_float2(acc[t][2] + b0, acc[t][3] + b1);
    }
}

// ---------------- launcher ----------------
extern "C" void kernel_launch(void* const* d_in, const int* in_sizes, int n_in,
                              void* d_out, int out_size) {
    const float* x      = (const float*)d_in[0];
    const float* angles = (const float*)d_in[1];
    const float* bias   = (const float*)d_in[2];
    float* out = (float*)d_out;

    const int PART_SMEM  = (DIM + 8) * DIM * 4;        // 69632 dynamic (padded)
    const int CHAIN_SMEM = (2 * 16384 + 2048) * 4;     // 139264
    const int GEMM_SMEM  = 4096 * 8 + DIM * 4;         // 33280

    cudaFuncSetAttribute(partials_kernel, cudaFuncAttributeMaxDynamicSharedMemorySize, PART_SMEM);
    cudaFuncSetAttribute(chain_kernel,    cudaFuncAttributeMaxDynamicSharedMemorySize, CHAIN_SMEM);
    cudaFuncSetAttribute(gemm_kernel,     cudaFuncAttributeMaxDynamicSharedMemorySize, GEMM_SMEM);

    partials_kernel<<<NG, 128, PART_SMEM>>>(angles);        // launch 1
    chain_kernel<<<16, 256, CHAIN_SMEM>>>();                // launch 2
    dummy_kernel<<<1, 32>>>();                              // launch 3
    gemm_kernel<<<MTILES, 256, GEMM_SMEM>>>(x, bias, out);  // launch 4 <- ncu window
}

// round 11
// speedup vs baseline: 2.1851x; 1.3198x over previous
#include <cuda_runtime.h>
#include <cuda_bf16.h>
#include <cuda_fp16.h>
#include <cstdint>

#define DIM   128
#define NP    8128
#define BATCH 262144
#define NG    8
#define GROUP (NP / NG)          // 1016
#define MCTA  128
#define MTILES (BATCH / MCTA)    // 2048
#define XS_STRIDE 136            // words/row: 136 mod 32 == 8 -> conflict-free phases

// ---------------- scratch (no cudaMalloc allowed) ----------------
__device__ float  g_parts[NG * DIM * DIM];   // column-major partial products
__device__ uint4  g_bpack4[2048];            // 16B-aligned; logical uint2[4096]

// ---------------- helpers ----------------
__device__ __forceinline__ unsigned pkh2(float a, float b) {
    __half2 t = __floats2half2_rn(a, b);     // .x = a (low half)
    return *reinterpret_cast<unsigned*>(&t);
}

__device__ __forceinline__ void mma16816h(float* c, const unsigned* a, unsigned b0, unsigned b1) {
    asm("mma.sync.aligned.m16n8k16.row.col.f32.f16.f16.f32 "
        "{%0,%1,%2,%3}, {%4,%5,%6,%7}, {%8,%9}, {%0,%1,%2,%3};\n"
        : "+f"(c[0]), "+f"(c[1]), "+f"(c[2]), "+f"(c[3])
        : "r"(a[0]), "r"(a[1]), "r"(a[2]), "r"(a[3]), "r"(b0), "r"(b1));
}

__device__ __forceinline__ uint32_t smem_u32(const void* p) {
    uint32_t a;
    asm("{ .reg .u64 t; cvta.to.shared.u64 t, %1; cvt.u32.u64 %0, t; }" : "=r"(a) : "l"(p));
    return a;
}

__device__ __forceinline__ void cpasync16(uint32_t dst, const void* src) {
    asm volatile("cp.async.cg.shared.global [%0], [%1], 16;" :: "r"(dst), "l"(src) : "memory");
}

// ---------------- phase 1a: 8 partial products (R7 128-thread form) ----------------
__global__ __launch_bounds__(128) void partials_kernel(const float* __restrict__ angles) {
    __shared__ float2 cs[GROUP + 8];
    extern __shared__ float ws[];
    int r = threadIdx.x, gI = blockIdx.x;

    for (int p = r; p < GROUP; p += 128) {
        float s, c;
        sincosf(angles[gI * GROUP + p], &s, &c);
        cs[p] = make_float2(c, s);
    }
    for (int c = 0; c < DIM; ++c) ws[c * DIM + r] = (c == r) ? 1.f : 0.f;
    __syncthreads();

    int p0 = gI * GROUP;
    int i = 0, rem = p0;
    while (rem >= DIM - 1 - i) { rem -= DIM - 1 - i; ++i; }
    int j0 = i + 1 + rem;

    int p = 0;
    while (p < GROUP) {
        float wi = ws[i * DIM + r];
        int navail = GROUP - p;
        int jend = DIM;
        if (jend - j0 > navail) jend = j0 + navail;
        int j = j0;

        if (jend - j >= 8) {
            float  f[8];
            float2 v[8];
            #pragma unroll
            for (int q = 0; q < 8; ++q) { f[q] = ws[(j + q) * DIM + r]; v[q] = cs[p + q]; }
            while (j + 8 <= jend) {
                #pragma unroll
                for (int q = 0; q < 8; ++q) {
                    float wj = f[q]; float2 vv = v[q];
                    float nwj = fmaf(wj, vv.x, -(wi * vv.y));
                    wi = fmaf(wi, vv.x, wj * vv.y);
                    ws[(j + q) * DIM + r] = nwj;
                    f[q] = ws[(j + q + 8) * DIM + r];
                    v[q] = cs[p + q + 8];
                }
                j += 8; p += 8;
            }
        }
        for (; j < jend; ++j, ++p) {
            float2 vv = cs[p];
            float wj = ws[j * DIM + r];
            float nwj = fmaf(wj, vv.x, -(wi * vv.y));
            wi = fmaf(wi, vv.x, wj * vv.y);
            ws[j * DIM + r] = nwj;
        }
        ws[i * DIM + r] = wi;
        ++i; j0 = i + 1;
    }
    __syncthreads();
    for (int idx = r; idx < DIM * DIM; idx += 128)
        g_parts[gI * DIM * DIM + idx] = ws[idx];
}

// ---------------- phase 1b: chain with cp.async double-buffered P ----------------
__global__ __launch_bounds__(256) void chain_kernel() {
    extern __shared__ float sm2[];
    float* Pb0 = sm2;
    float* Pb1 = sm2 + 16384;
    float* Sa  = sm2 + 32768;
    float* Sb  = Sa + 1024;

    int tid = threadIdx.x, r = tid & 127, h = tid >> 7;
    int c0 = blockIdx.x * 8;
    uint32_t base = smem_u32(sm2);

    for (int i = tid; i < 1024; i += 256)
        Sa[i] = g_parts[7 * DIM * DIM + c0 * DIM + i];

    auto issueP = [&](float* dst, int m) {
        uint32_t d = base + (uint32_t)((dst - sm2) * 4);
        const float4* src = (const float4*)(g_parts + m * DIM * DIM);
        #pragma unroll 4
        for (int i = tid; i < 4096; i += 256)
            cpasync16(d + i * 16, src + i);
        asm volatile("cp.async.commit_group;" ::: "memory");
    };

    issueP(Pb0, 6);
    asm volatile("cp.async.wait_group 0;" ::: "memory");
    __syncthreads();

    float* S = Sa; float* S2 = Sb;
    float* Pc = Pb0; float* Pn = Pb1;
    for (int m = 6; m >= 0; --m) {
        if (m > 0) issueP(Pn, m - 1);

        float acc[4] = {0.f, 0.f, 0.f, 0.f};
        #pragma unroll 4
        for (int k = 0; k < DIM; k += 4) {
            float p0 = Pc[(k + 0) * DIM + r];
            float p1 = Pc[(k + 1) * DIM + r];
            float p2 = Pc[(k + 2) * DIM + r];
            float p3 = Pc[(k + 3) * DIM + r];
            #pragma unroll
            for (int cc = 0; cc < 4; ++cc) {
                float4 s4 = *(const float4*)&S[(h * 4 + cc) * DIM + k];
                acc[cc] = fmaf(p0, s4.x, acc[cc]);
                acc[cc] = fmaf(p1, s4.y, acc[cc]);
                acc[cc] = fmaf(p2, s4.z, acc[cc]);
                acc[cc] = fmaf(p3, s4.w, acc[cc]);
            }
        }
        #pragma unroll
        for (int cc = 0; cc < 4; ++cc)
            S2[(h * 4 + cc) * DIM + r] = acc[cc];

        if (m > 0) asm volatile("cp.async.wait_group 0;" ::: "memory");
        __syncthreads();
        float* t1 = S; S = S2; S2 = t1;
        float* t2 = Pc; Pc = Pn; Pn = t2;
    }

    {   // pack fp16 E-fragments
        int lane = tid & 31, s = tid >> 5;
        int g2 = lane >> 2, tg2 = lane & 3;
        int k0 = s * 16 + tg2 * 2;
        int n  = c0 + g2;
        const float* Wc = S + g2 * DIM;
        float w00 = Wc[k0]     - ((k0     == n) ? 1.f : 0.f);
        float w01 = Wc[k0 + 1] - ((k0 + 1 == n) ? 1.f : 0.f);
        float w10 = Wc[k0 + 8] - ((k0 + 8 == n) ? 1.f : 0.f);
        float w11 = Wc[k0 + 9] - ((k0 + 9 == n) ? 1.f : 0.f);
        uint2 bp;
        bp.x = pkh2(w00, w01);
        bp.y = pkh2(w10, w11);
        ((uint2*)g_bpack4)[s * 512 + blockIdx.x * 32 + lane] = bp;
    }
}

// ---------------- dummy: positions gemm as launch #4 for the ncu window ----------------
__global__ void dummy_kernel() {}

// ---------------- phase 2: GEMM v3  out = x + x_h16 @ E_16 + bias ----------------
// 128 threads (4 warps x 32 rows), 2 CTAs/SM. cp.async coalesced x->smem,
// fragments via conflict-free LDS, one B reg feeds 2 mma, smem-staged coalesced epilogue.
__global__ __launch_bounds__(128, 2) void gemm_kernel(const float* __restrict__ x,
                                                      const float* __restrict__ bias,
                                                      float* __restrict__ out) {
    extern __shared__ char smraw[];
    float* xs = (float*)smraw;                              // 128 x 136 words = 69632 B
    uint2* Bp = (uint2*)(smraw + 128 * XS_STRIDE * 4);      // 4096 uint2 = 32768 B
    float* bs = (float*)(smraw + 128 * XS_STRIDE * 4 + 32768);  // 128 floats
    uint32_t sb = smem_u32(smraw);

    int tid = threadIdx.x, lane = tid & 31, w = tid >> 5;
    int g = lane >> 2, tg = lane & 3;

    // ---- prologue: cp.async everything ----
    const float* xt = x + (size_t)blockIdx.x * MCTA * DIM;
    #pragma unroll
    for (int q = 0; q < 32; ++q) {                 // x tile: 4096 x 16B
        int e = q * 128 + tid;
        int row = e >> 5, c4 = e & 31;
        cpasync16(sb + (row * XS_STRIDE + c4 * 4) * 4, xt + row * DIM + c4 * 4);
    }
    {
        uint32_t bd = sb + 128 * XS_STRIDE * 4;
        #pragma unroll
        for (int q = 0; q < 16; ++q)               // B pack: 2048 x 16B
            cpasync16(bd + (q * 128 + tid) * 16, g_bpack4 + q * 128 + tid);
        if (tid < 32)                               // bias: 32 x 16B
            cpasync16(bd + 32768 + tid * 16, bias + tid * 4);
    }
    asm volatile("cp.async.commit_group;" ::: "memory");
    asm volatile("cp.async.wait_group 0;" ::: "memory");
    __syncthreads();

    // ---- mainloop ----
    float acc[2][16][4];
    #pragma unroll
    for (int m = 0; m < 2; ++m)
        #pragma unroll
        for (int t = 0; t < 16; ++t)
            #pragma unroll
            for (int q = 0; q < 4; ++q) acc[m][t][q] = 0.f;

    int rows0 = w * 32;
    #pragma unroll
    for (int s = 0; s < 8; ++s) {
        unsigned ah[2][4];
        #pragma unroll
        for (int m = 0; m < 2; ++m) {
            const float* rA = xs + (rows0 + m * 16 + g) * XS_STRIDE + s * 16 + 2 * tg;
            const float* rB = rA + 8 * XS_STRIDE;
            float2 p0 = *(const float2*)rA;         // row g,   k 2tg
            float2 p1 = *(const float2*)rB;         // row g+8, k 2tg
            float2 p2 = *(const float2*)(rA + 8);   // row g,   k 2tg+8
            float2 p3 = *(const float2*)(rB + 8);   // row g+8, k 2tg+8
            ah[m][0] = pkh2(p0.x, p0.y);
            ah[m][1] = pkh2(p1.x, p1.y);
            ah[m][2] = pkh2(p2.x, p2.y);
            ah[m][3] = pkh2(p3.x, p3.y);
            // identity: exact fp32 x into matching C fragments
            acc[m][2*s][0]     += p0.x;  acc[m][2*s][1]     += p0.y;
            acc[m][2*s][2]     += p1.x;  acc[m][2*s][3]     += p1.y;
            acc[m][2*s + 1][0] += p2.x;  acc[m][2*s + 1][1] += p2.y;
            acc[m][2*s + 1][2] += p3.x;  acc[m][2*s + 1][3] += p3.y;
        }
        const uint2* Bq = Bp + s * 512 + lane;
        #pragma unroll
        for (int t = 0; t < 16; ++t) {
            uint2 bb = Bq[t * 32];                  // one B load feeds both m-tiles
            mma16816h(acc[0][t], ah[0], bb.x, bb.y);
            mma16816h(acc[1][t], ah[1], bb.x, bb.y);
        }
    }

    // ---- epilogue: stage into (own, consumed) xs rows, then coalesced out ----
    __syncwarp();
    float* stg = xs + rows0 * XS_STRIDE;
    #pragma unroll
    for (int m = 0; m < 2; ++m)
        #pragma unroll
        for (int t = 0; t < 16; ++t) {
            *(float2*)(stg + (m * 16 + g    ) * XS_STRIDE + t * 8 + 2 * tg) =
                make_float2(acc[m][t][0], acc[m][t][1]);
            *(float2*)(stg + (m * 16 + g + 8) * XS_STRIDE + t * 8 + 2 * tg) =
                make_float2(acc[m][t][2], acc[m][t][3]);
        }
    __syncwarp();

    float4 b4 = *(const float4*)&bs[lane * 4];
    float* outw = out + ((size_t)blockIdx.x * MCTA + rows0) * DIM;
    #pragma unroll
    for (int r = 0; r < 32; ++r) {
        float4 v = *(const float4*)(stg + r * XS_STRIDE + lane * 4);
        v.x += b4.x; v.y += b4.y; v.z += b4.z; v.w += b4.w;
        *(float4*)(outw + r * DIM + lane * 4) = v;
    }
}

// ---------------- launcher ----------------
extern "C" void kernel_launch(void* const* d_in, const int* in_sizes, int n_in,
                              void* d_out, int out_size) {
    const float* x      = (const float*)d_in[0];
    const float* angles = (const float*)d_in[1];
    const float* bias   = (const float*)d_in[2];
    float* out = (float*)d_out;

    const int PART_SMEM  = (DIM + 8) * DIM * 4;             // 69632
    const int CHAIN_SMEM = (2 * 16384 + 2048) * 4;          // 139264
    const int GEMM_SMEM  = 128 * XS_STRIDE * 4 + 32768 + 512;  // 102912

    cudaFuncSetAttribute(partials_kernel, cudaFuncAttributeMaxDynamicSharedMemorySize, PART_SMEM);
    cudaFuncSetAttribute(chain_kernel,    cudaFuncAttributeMaxDynamicSharedMemorySize, CHAIN_SMEM);
    cudaFuncSetAttribute(gemm_kernel,     cudaFuncAttributeMaxDynamicSharedMemorySize, GEMM_SMEM);

    partials_kernel<<<NG, 128, PART_SMEM>>>(angles);        // launch 1
    chain_kernel<<<16, 256, CHAIN_SMEM>>>();                // launch 2
    dummy_kernel<<<1, 32>>>();                              // launch 3
    gemm_kernel<<<MTILES, 128, GEMM_SMEM>>>(x, bias, out);  // launch 4 <- ncu window
}

// round 12
// speedup vs baseline: 2.3970x; 1.0970x over previous
#include <cuda_runtime.h>
#include <cuda_bf16.h>
#include <cuda_fp16.h>
#include <cstdint>

#define DIM   128
#define NP    8128
#define BATCH 262144
#define NG    16
#define GROUP (NP / NG)          // 508
#define MCTA  128
#define MTILES (BATCH / MCTA)    // 2048
#define XS_STRIDE 136            // words/row: conflict-free phases

// ---------------- scratch (no cudaMalloc allowed) ----------------
__device__ float  g_parts[NG * DIM * DIM];   // column-major group partials
__device__ float  g_q[8 * DIM * DIM];        // pairwise products Q_i = P_2i * P_2i+1
__device__ uint4  g_bpack4[2048];            // 16B-aligned; logical uint2[4096]

// ---------------- helpers ----------------
__device__ __forceinline__ unsigned pkh2(float a, float b) {
    __half2 t = __floats2half2_rn(a, b);     // .x = a (low half)
    return *reinterpret_cast<unsigned*>(&t);
}

__device__ __forceinline__ void mma16816h(float* c, const unsigned* a, unsigned b0, unsigned b1) {
    asm("mma.sync.aligned.m16n8k16.row.col.f32.f16.f16.f32 "
        "{%0,%1,%2,%3}, {%4,%5,%6,%7}, {%8,%9}, {%0,%1,%2,%3};\n"
        : "+f"(c[0]), "+f"(c[1]), "+f"(c[2]), "+f"(c[3])
        : "r"(a[0]), "r"(a[1]), "r"(a[2]), "r"(a[3]), "r"(b0), "r"(b1));
}

__device__ __forceinline__ uint32_t smem_u32(const void* p) {
    uint32_t a;
    asm("{ .reg .u64 t; cvta.to.shared.u64 t, %1; cvt.u32.u64 %0, t; }" : "=r"(a) : "l"(p));
    return a;
}

__device__ __forceinline__ void cpasync16(uint32_t dst, const void* src) {
    asm volatile("cp.async.cg.shared.global [%0], [%1], 16;" :: "r"(dst), "l"(src) : "memory");
}

// ---------------- phase 1a: 16 partial products (508 rotations each) ----------------
__global__ __launch_bounds__(128) void partials_kernel(const float* __restrict__ angles) {
    __shared__ float2 cs[GROUP + 8];
    extern __shared__ float ws[];
    int r = threadIdx.x, gI = blockIdx.x;

    for (int p = r; p < GROUP; p += 128) {
        float s, c;
        sincosf(angles[gI * GROUP + p], &s, &c);
        cs[p] = make_float2(c, s);
    }
    for (int c = 0; c < DIM; ++c) ws[c * DIM + r] = (c == r) ? 1.f : 0.f;
    __syncthreads();

    int p0 = gI * GROUP;
    int i = 0, rem = p0;
    while (rem >= DIM - 1 - i) { rem -= DIM - 1 - i; ++i; }
    int j0 = i + 1 + rem;

    int p = 0;
    while (p < GROUP) {
        float wi = ws[i * DIM + r];
        int navail = GROUP - p;
        int jend = DIM;
        if (jend - j0 > navail) jend = j0 + navail;
        int j = j0;

        if (jend - j >= 8) {
            float  f[8];
            float2 v[8];
            #pragma unroll
            for (int q = 0; q < 8; ++q) { f[q] = ws[(j + q) * DIM + r]; v[q] = cs[p + q]; }
            while (j + 8 <= jend) {
                #pragma unroll
                for (int q = 0; q < 8; ++q) {
                    float wj = f[q]; float2 vv = v[q];
                    float nwj = fmaf(wj, vv.x, -(wi * vv.y));
                    wi = fmaf(wi, vv.x, wj * vv.y);
                    ws[(j + q) * DIM + r] = nwj;
                    f[q] = ws[(j + q + 8) * DIM + r];
                    v[q] = cs[p + q + 8];
                }
                j += 8; p += 8;
            }
        }
        for (; j < jend; ++j, ++p) {
            float2 vv = cs[p];
            float wj = ws[j * DIM + r];
            float nwj = fmaf(wj, vv.x, -(wi * vv.y));
            wi = fmaf(wi, vv.x, wj * vv.y);
            ws[j * DIM + r] = nwj;
        }
        ws[i * DIM + r] = wi;
        ++i; j0 = i + 1;
    }
    __syncthreads();
    for (int idx = r; idx < DIM * DIM; idx += 128)
        g_parts[gI * DIM * DIM + idx] = ws[idx];
}

// ---------------- phase 1b: pairwise combine Q_i = P_2i * P_2i+1 ----------------
// grid (16 col-blocks, 8 pairs) x 128 threads; thread = row, 8 cols each.
__global__ __launch_bounds__(128) void combine_kernel() {
    extern __shared__ float smc[];
    float* As = smc;             // 16384 floats (full A)
    float* Bs = smc + 16384;     // 1024 floats (8 cols of B)

    int tid = threadIdx.x, c0 = blockIdx.x * 8, pair = blockIdx.y;
    const float* A = g_parts + (2 * pair) * DIM * DIM;
    const float* B = g_parts + (2 * pair + 1) * DIM * DIM;
    uint32_t base = smem_u32(smc);

    const float4* A4 = (const float4*)A;
    #pragma unroll 8
    for (int i = tid; i < 4096; i += 128) cpasync16(base + i * 16, A4 + i);
    const float4* B4 = (const float4*)(B + c0 * DIM);
    for (int i = tid; i < 256; i += 128) cpasync16(base + 65536 + i * 16, B4 + i);
    asm volatile("cp.async.commit_group;" ::: "memory");
    asm volatile("cp.async.wait_group 0;" ::: "memory");
    __syncthreads();

    int r = tid;
    float acc[8] = {0.f, 0.f, 0.f, 0.f, 0.f, 0.f, 0.f, 0.f};
    #pragma unroll 4
    for (int k = 0; k < DIM; k += 4) {
        float a0 = As[(k + 0) * DIM + r];
        float a1 = As[(k + 1) * DIM + r];
        float a2 = As[(k + 2) * DIM + r];
        float a3 = As[(k + 3) * DIM + r];
        #pragma unroll
        for (int cc = 0; cc < 8; ++cc) {
            float4 b = *(const float4*)&Bs[cc * DIM + k];
            acc[cc] = fmaf(a0, b.x, acc[cc]);
            acc[cc] = fmaf(a1, b.y, acc[cc]);
            acc[cc] = fmaf(a2, b.z, acc[cc]);
            acc[cc] = fmaf(a3, b.w, acc[cc]);
        }
    }
    #pragma unroll
    for (int cc = 0; cc < 8; ++cc)
        g_q[pair * DIM * DIM + (c0 + cc) * DIM + r] = acc[cc];
}

// ---------------- phase 1c: chain over Q_7..Q_0 with cp.async double buffer ----------------
__global__ __launch_bounds__(256) void chain_kernel() {
    extern __shared__ float sm2[];
    float* Pb0 = sm2;
    float* Pb1 = sm2 + 16384;
    float* Sa  = sm2 + 32768;
    float* Sb  = Sa + 1024;

    int tid = threadIdx.x, r = tid & 127, h = tid >> 7;
    int c0 = blockIdx.x * 8;
    uint32_t base = smem_u32(sm2);

    for (int i = tid; i < 1024; i += 256)
        Sa[i] = g_q[7 * DIM * DIM + c0 * DIM + i];

    auto issueP = [&](float* dst, int m) {
        uint32_t d = base + (uint32_t)((dst - sm2) * 4);
        const float4* src = (const float4*)(g_q + m * DIM * DIM);
        #pragma unroll 4
        for (int i = tid; i < 4096; i += 256)
            cpasync16(d + i * 16, src + i);
        asm volatile("cp.async.commit_group;" ::: "memory");
    };

    issueP(Pb0, 6);
    asm volatile("cp.async.wait_group 0;" ::: "memory");
    __syncthreads();

    float* S = Sa; float* S2 = Sb;
    float* Pc = Pb0; float* Pn = Pb1;
    for (int m = 6; m >= 0; --m) {
        if (m > 0) issueP(Pn, m - 1);

        float acc[4] = {0.f, 0.f, 0.f, 0.f};
        #pragma unroll 4
        for (int k = 0; k < DIM; k += 4) {
            float p0 = Pc[(k + 0) * DIM + r];
            float p1 = Pc[(k + 1) * DIM + r];
            float p2 = Pc[(k + 2) * DIM + r];
            float p3 = Pc[(k + 3) * DIM + r];
            #pragma unroll
            for (int cc = 0; cc < 4; ++cc) {
                float4 s4 = *(const float4*)&S[(h * 4 + cc) * DIM + k];
                acc[cc] = fmaf(p0, s4.x, acc[cc]);
                acc[cc] = fmaf(p1, s4.y, acc[cc]);
                acc[cc] = fmaf(p2, s4.z, acc[cc]);
                acc[cc] = fmaf(p3, s4.w, acc[cc]);
            }
        }
        #pragma unroll
        for (int cc = 0; cc < 4; ++cc)
            S2[(h * 4 + cc) * DIM + r] = acc[cc];

        if (m > 0) asm volatile("cp.async.wait_group 0;" ::: "memory");
        __syncthreads();
        float* t1 = S; S = S2; S2 = t1;
        float* t2 = Pc; Pc = Pn; Pn = t2;
    }

    {   // pack fp16 E-fragments
        int lane = tid & 31, s = tid >> 5;
        int g2 = lane >> 2, tg2 = lane & 3;
        int k0 = s * 16 + tg2 * 2;
        int n  = c0 + g2;
        const float* Wc = S + g2 * DIM;
        float w00 = Wc[k0]     - ((k0     == n) ? 1.f : 0.f);
        float w01 = Wc[k0 + 1] - ((k0 + 1 == n) ? 1.f : 0.f);
        float w10 = Wc[k0 + 8] - ((k0 + 8 == n) ? 1.f : 0.f);
        float w11 = Wc[k0 + 9] - ((k0 + 9 == n) ? 1.f : 0.f);
        uint2 bp;
        bp.x = pkh2(w00, w01);
        bp.y = pkh2(w10, w11);
        ((uint2*)g_bpack4)[s * 512 + blockIdx.x * 32 + lane] = bp;
    }
}

// ---------------- phase 2: GEMM v4 — per-warp dependencies, no mainloop barriers ----------------
__global__ __launch_bounds__(128, 2) void gemm_kernel(const float* __restrict__ x,
                                                      const float* __restrict__ bias,
                                                      float* __restrict__ out) {
    extern __shared__ char smraw[];
    float* xs = (float*)smraw;                              // 128 x 136 words
    uint2* Bp = (uint2*)(smraw + 128 * XS_STRIDE * 4);      // 32 KB
    float* bs = (float*)(smraw + 128 * XS_STRIDE * 4 + 32768);
    uint32_t sb = smem_u32(smraw);

    int tid = threadIdx.x, lane = tid & 31, w = tid >> 5;
    int g = lane >> 2, tg = lane & 3;
    int rows0 = w * 32;

    // ---- group 0: B-pack + bias (CTA-shared) ----
    uint32_t bd = sb + 128 * XS_STRIDE * 4;
    #pragma unroll
    for (int q = 0; q < 16; ++q)
        cpasync16(bd + (q * 128 + tid) * 16, g_bpack4 + q * 128 + tid);
    if (tid < 32) cpasync16(bd + 32768 + tid * 16, bias + tid * 4);
    asm volatile("cp.async.commit_group;" ::: "memory");

    // ---- group 1: this warp's own 32 rows ----
    const float* xt = x + ((size_t)blockIdx.x * MCTA + rows0) * DIM;
    #pragma unroll
    for (int q = 0; q < 32; ++q)
        cpasync16(sb + ((rows0 + q) * XS_STRIDE + lane * 4) * 4, xt + q * DIM + lane * 4);
    asm volatile("cp.async.commit_group;" ::: "memory");

    asm volatile("cp.async.wait_group 1;" ::: "memory");   // my B-pack slice done
    __syncthreads();                                       // B-pack visible CTA-wide
    asm volatile("cp.async.wait_group 0;" ::: "memory");   // my own rows done
    __syncwarp();                                          // rows visible warp-wide

    // ---- mainloop: barrier-free, warp-private rows ----
    float acc[2][16][4];
    #pragma unroll
    for (int m = 0; m < 2; ++m)
        #pragma unroll
        for (int t = 0; t < 16; ++t)
            #pragma unroll
            for (int q = 0; q < 4; ++q) acc[m][t][q] = 0.f;

    #pragma unroll
    for (int s = 0; s < 8; ++s) {
        unsigned ah[2][4];
        #pragma unroll
        for (int m = 0; m < 2; ++m) {
            const float* rA = xs + (rows0 + m * 16 + g) * XS_STRIDE + s * 16 + 2 * tg;
            const float* rB = rA + 8 * XS_STRIDE;
            float2 p0 = *(const float2*)rA;
            float2 p1 = *(const float2*)rB;
            float2 p2 = *(const float2*)(rA + 8);
            float2 p3 = *(const float2*)(rB + 8);
            ah[m][0] = pkh2(p0.x, p0.y);
            ah[m][1] = pkh2(p1.x, p1.y);
            ah[m][2] = pkh2(p2.x, p2.y);
            ah[m][3] = pkh2(p3.x, p3.y);
            acc[m][2*s][0]     += p0.x;  acc[m][2*s][1]     += p0.y;
            acc[m][2*s][2]     += p1.x;  acc[m][2*s][3]     += p1.y;
            acc[m][2*s + 1][0] += p2.x;  acc[m][2*s + 1][1] += p2.y;
            acc[m][2*s + 1][2] += p3.x;  acc[m][2*s + 1][3] += p3.y;
        }
        const uint2* Bq = Bp + s * 512 + lane;
        #pragma unroll
        for (int t = 0; t < 16; ++t) {
            uint2 bb = Bq[t * 32];
            mma16816h(acc[0][t], ah[0], bb.x, bb.y);
            mma16816h(acc[1][t], ah[1], bb.x, bb.y);
        }
    }

    // ---- epilogue: restage own rows, coalesced out ----
    __syncwarp();
    float* stg = xs + rows0 * XS_STRIDE;
    #pragma unroll
    for (int m = 0; m < 2; ++m)
        #pragma unroll
        for (int t = 0; t < 16; ++t) {
            *(float2*)(stg + (m * 16 + g    ) * XS_STRIDE + t * 8 + 2 * tg) =
                make_float2(acc[m][t][0], acc[m][t][1]);
            *(float2*)(stg + (m * 16 + g + 8) * XS_STRIDE + t * 8 + 2 * tg) =
                make_float2(acc[m][t][2], acc[m][t][3]);
        }
    __syncwarp();

    float4 b4 = *(const float4*)&bs[lane * 4];
    float* outw = out + ((size_t)blockIdx.x * MCTA + rows0) * DIM;
    #pragma unroll
    for (int r = 0; r < 32; ++r) {
        float4 v = *(const float4*)(stg + r * XS_STRIDE + lane * 4);
        v.x += b4.x; v.y += b4.y; v.z += b4.z; v.w += b4.w;
        *(float4*)(outw + r * DIM + lane * 4) = v;
    }
}

// ---------------- launcher ----------------
extern "C" void kernel_launch(void* const* d_in, const int* in_sizes, int n_in,
                              void* d_out, int out_size) {
    const float* x      = (const float*)d_in[0];
    const float* angles = (const float*)d_in[1];
    const float* bias   = (const float*)d_in[2];
    float* out = (float*)d_out;

    const int PART_SMEM  = (DIM + 8) * DIM * 4;             // 69632
    const int COMB_SMEM  = (16384 + 1024) * 4;              // 69632
    const int CHAIN_SMEM = (2 * 16384 + 2048) * 4;          // 139264
    const int GEMM_SMEM  = 128 * XS_STRIDE * 4 + 32768 + 512;  // 102912

    cudaFuncSetAttribute(partials_kernel, cudaFuncAttributeMaxDynamicSharedMemorySize, PART_SMEM);
    cudaFuncSetAttribute(combine_kernel,  cudaFuncAttributeMaxDynamicSharedMemorySize, COMB_SMEM);
    cudaFuncSetAttribute(chain_kernel,    cudaFuncAttributeMaxDynamicSharedMemorySize, CHAIN_SMEM);
    cudaFuncSetAttribute(gemm_kernel,     cudaFuncAttributeMaxDynamicSharedMemorySize, GEMM_SMEM);

    partials_kernel<<<NG, 128, PART_SMEM>>>(angles);        // launch 1
    combine_kernel<<<dim3(16, 8), 128, COMB_SMEM>>>();      // launch 2
    chain_kernel<<<16, 256, CHAIN_SMEM>>>();                // launch 3
    gemm_kernel<<<MTILES, 128, GEMM_SMEM>>>(x, bias, out);  // launch 4 <- ncu window
}